// round 16
// baseline (speedup 1.0000x reference)
#include <cuda_runtime.h>
#include <stdint.h>

#define Dm 256
#define Bm 16384
#define NSTEPS 5
#define Mrows 8
#define NW 8
#define LCAP 264

#define SIGNB 0x80000000
#define PADB  0x40000000
#define OFMASK 0x0003FC00   // idx<<10 (byte offset of W row) for idx<256

// ---- flag-independent fp32 exp/log/sigmoid (pure FMA; sigmoid keeps __fdiv_rn) ----

static __device__ __forceinline__ float my_exp(float x) {
    x = fmaxf(x, -80.0f);
    float z = x * 1.4426950408889634f;
    float n = rintf(z);
    float r = fmaf(n, -0.693359375f, x);
    r = fmaf(n, 2.12194440054690583e-4f, r);
    float p = 1.9841269841269841e-4f;
    p = fmaf(p, r, 1.3888888888888889e-3f);
    p = fmaf(p, r, 8.3333333333333333e-3f);
    p = fmaf(p, r, 4.1666666666666664e-2f);
    p = fmaf(p, r, 1.6666666666666666e-1f);
    p = fmaf(p, r, 0.5f);
    p = fmaf(p, r, 1.0f);
    p = fmaf(p, r, 1.0f);
    int ni = (int)n;
    return p * __int_as_float((127 + ni) << 23);
}

static __device__ __forceinline__ float my_log(float v) {
    int i = __float_as_int(v);
    int e = (i - 0x3f3504f3) >> 23;
    float m = __int_as_float(i - (e << 23));
    float f = m - 1.0f;
    float z = f * f;
    float p = 7.0376836292e-2f;
    p = fmaf(p, f, -1.1514610310e-1f);
    p = fmaf(p, f, 1.1676998740e-1f);
    p = fmaf(p, f, -1.2420140846e-1f);
    p = fmaf(p, f, 1.4249322787e-1f);
    p = fmaf(p, f, -1.6668057665e-1f);
    p = fmaf(p, f, 2.0000714765e-1f);
    p = fmaf(p, f, -2.4999993993e-1f);
    p = fmaf(p, f, 3.3333331174e-1f);
    float r = fmaf(p * z, f, fmaf(-0.5f, z, f));
    float ef = (float)e;
    return fmaf(ef, 0.693359375f, fmaf(ef, -2.12194440054690583e-4f, r));
}

static __device__ __forceinline__ float my_sigmoid(float t) {   // decision-critical: unchanged
    float en = my_exp(-fabsf(t));
    float s = __fdiv_rn(en, 1.0f + en);
    return (t > 0.0f) ? 1.0f - s : s;
}

static __device__ __forceinline__ float sxor(float w, int e) {  // w * sign(e) via bit xor
    return __int_as_float(__float_as_int(w) ^ (e & SIGNB));
}

// ---- fused sampler: one block = 8 chains; thread d owns dim d for math,
// ---- gathers re-map to (64 dim-quads x 4 row-pairs) with LDG.128 ----

__global__ void __launch_bounds__(256, 4)
els_kernel(const float* __restrict__ x_in, const float* __restrict__ xa_in,
           const float* __restrict__ Wm, const float* __restrict__ bv,
           const float* __restrict__ rr, const float* __restrict__ noise,
           const float* __restrict__ au, float* __restrict__ out)
{
    const int d = threadIdx.x;
    const int warp = d >> 5;
    const int lane = d & 31;
    const int rowBase = blockIdx.x * Mrows;

    __shared__ float   xh[Mrows * Dm];         // h state, [m*256 + d]
    __shared__ unsigned posw[Mrows][NW];
    __shared__ unsigned negw[Mrows][NW];
    __shared__ int     flist[Mrows][LCAP];     // packed: sign | (idx<<10); PADB = pad
    __shared__ int     fcnt[Mrows];            // exact count
    __shared__ float   red[Mrows][NW];
    __shared__ float   xdas[Mrows][Dm];
    __shared__ float   taccs[Mrows][Dm];
    __shared__ float   h2s[Mrows][Dm];

    const float bd = bv[d];
    float xa[Mrows];
    unsigned xmask = 0;

    // ---- load x/xa; ballot x-bits into posw (init "flip list" = ones of x) ----
    #pragma unroll
    for (int m = 0; m < Mrows; m++) {
        float xv = __ldcs(&x_in[(size_t)(rowBase + m) * Dm + d]);
        xa[m] = __ldcs(&xa_in[(size_t)(rowBase + m) * Dm + d]);
        bool one = xv != 0.0f;
        if (one) xmask |= (1u << m);
        unsigned pb = __ballot_sync(0xffffffffu, one);
        if (lane == 0) { posw[m][warp] = pb; negw[m][warp] = 0u; }
    }
    // prefetch step-0 rr/noise lines + au lines into L2 while init runs
    if (lane == 0) {
        size_t base0 = (size_t)rowBase * Dm + (warp << 5);
        #pragma unroll
        for (int m = 0; m < Mrows; m++) {
            asm volatile("prefetch.global.L2 [%0];" :: "l"(rr + base0 + (size_t)m * Dm));
            asm volatile("prefetch.global.L2 [%0];" :: "l"(noise + base0 + (size_t)m * Dm));
        }
    }
    if (d == 0) {
        #pragma unroll
        for (int s = 0; s < NSTEPS; s++)
            asm volatile("prefetch.global.L2 [%0];" :: "l"(au + (size_t)s * Bm + rowBase));
    }
    __syncthreads();

    // ---- build init lists (64 threads; negw==0 -> pos only + pad) ----
    if (d < Mrows * NW) {
        int m = d >> 3, c = d & 7;
        int off = 0;
        #pragma unroll
        for (int c2 = 0; c2 < NW; c2++) {
            int cnt = __popc(posw[m][c2]);
            if (c2 < c) off += cnt;
        }
        int base = c * 32;
        unsigned pw = posw[m][c];
        while (pw) { int j = __ffs(pw) - 1; pw &= pw - 1; flist[m][off++] = (base + j) << 10; }
        if (c == NW - 1) {
            int padded = (off + 3) & ~3;
            for (int i = off; i < padded; i++) flist[m][i] = PADB;
            fcnt[m] = off;
        }
    }
    __syncthreads();

    // ---- init gather: h = sum_{e: x=1} W[e][:]  (== FMA loop skipping exact
    // ---- zeros, ascending e => bit-identical to the dense matvec) ----
    {
        const int g  = d & 63;
        const int rp = d >> 6;
        const char* wbase = (const char*)Wm + g * 16;
        #pragma unroll
        for (int t = 0; t < 2; t++) {
            const int m = rp + t * 4;
            const int cnt  = fcnt[m];
            const int full = cnt & ~3;
            const int* fl = flist[m];
            const int4* fl4 = reinterpret_cast<const int4*>(fl);
            float4 acc = make_float4(0.0f, 0.0f, 0.0f, 0.0f);
            int4 en = fl4[0];
            for (int i = 0; i < full; i += 4) {
                int4 e = en;
                en = fl4[(i >> 2) + 1];
                float4 w0 = *reinterpret_cast<const float4*>(wbase + (e.x & OFMASK));
                float4 w1 = *reinterpret_cast<const float4*>(wbase + (e.y & OFMASK));
                float4 w2 = *reinterpret_cast<const float4*>(wbase + (e.z & OFMASK));
                float4 w3 = *reinterpret_cast<const float4*>(wbase + (e.w & OFMASK));
                acc.x += w0.x; acc.y += w0.y; acc.z += w0.z; acc.w += w0.w;
                acc.x += w1.x; acc.y += w1.y; acc.z += w1.z; acc.w += w1.w;
                acc.x += w2.x; acc.y += w2.y; acc.z += w2.z; acc.w += w2.w;
                acc.x += w3.x; acc.y += w3.y; acc.z += w3.z; acc.w += w3.w;
            }
            if (cnt & 3) {
                #pragma unroll
                for (int j = 0; j < 4; j++) {
                    int e = fl[full + j];
                    float sv = (e & PADB) ? 0.0f : 1.0f;
                    float4 w = *reinterpret_cast<const float4*>(wbase + (e & OFMASK));
                    acc.x = fmaf(sv, w.x, acc.x);
                    acc.y = fmaf(sv, w.y, acc.y);
                    acc.z = fmaf(sv, w.z, acc.z);
                    acc.w = fmaf(sv, w.w, acc.w);
                }
            }
            *reinterpret_cast<float4*>(&xh[m * Dm + g * 4]) = acc;
        }
    }
    __syncthreads();

    for (int step = 0; step < NSTEPS; step++) {
        unsigned indmask = 0;

        // ---- stage 1: propose flips, forward log-prob terms ----
        #pragma unroll
        for (int m = 0; m < Mrows; m++) {
            float rv  = __ldcs(&rr[((size_t)(step * Bm + rowBase + m)) * Dm + d]);
            float nv  = __ldcs(&noise[((size_t)(step * Bm + rowBase + m)) * Dm + d]);
            float hm  = xh[m * Dm + d];
            float xf  = ((xmask >> m) & 1u) ? 1.0f : 0.0f;
            float sgn = 1.0f - 2.0f * xf;                    // -(2x-1)
            float ga  = (xf - xa[m]) * 1e-4f;                // (x - xa)/ETA
            float hb  = hm + bd;
            float gm  = (hb * sgn) * 0.5f - (ga * 0.5f) * sgn;
            float fp  = my_sigmoid(gm - 2.5f);
            bool ind  = rv < fp;
            float inner = xa[m] + 0.25f * ga;
            float pn  = __fmul_rn(0.70710678118654752f, nv);
            float xdav = inner + pn;
            float lpf = my_log((ind ? fp : 1.0f - fp) + 1e-10f);
            float e1  = (xf != 0.0f) ? fmaf(0.5f, hm, bd) : 0.0f;  // x*(0.5h+b)
            float dxa = xf - xa[m];
            float q1  = xdav - inner;
            taccs[m][d] = fmaf(dxa * dxa, 5e-5f, q1 * q1) - lpf - e1;
            if (ind) indmask |= (1u << m);
            unsigned pb = __ballot_sync(0xffffffffu, ind && xf == 0.0f);
            unsigned nb = __ballot_sync(0xffffffffu, ind && xf != 0.0f);
            if (lane == 0) { posw[m][warp] = pb; negw[m][warp] = nb; }
            xdas[m][d] = xdav;
        }
        __syncthreads();

        // ---- stage 1b: expand bitmasks into per-row packed flip lists ----
        // Order per row: chunk 0..7, pos asc then neg asc (bit-identical h2 order).
        if (d < Mrows * NW) {
            int m = d >> 3, c = d & 7;
            int off = 0;
            #pragma unroll
            for (int c2 = 0; c2 < NW; c2++) {
                int cnt = __popc(posw[m][c2]) + __popc(negw[m][c2]);
                if (c2 < c) off += cnt;
            }
            int base = c * 32;
            unsigned pw = posw[m][c];
            while (pw) { int j = __ffs(pw) - 1; pw &= pw - 1; flist[m][off++] = (base + j) << 10; }
            unsigned nw_ = negw[m][c];
            while (nw_) { int j = __ffs(nw_) - 1; nw_ &= nw_ - 1; flist[m][off++] = (int)(SIGNB | (unsigned)((base + j) << 10)); }
            if (c == NW - 1) {
                int padded = (off + 3) & ~3;
                for (int i = off; i < padded; i++) flist[m][i] = PADB;
                fcnt[m] = off;
            }
        }
        __syncthreads();

        // ---- stage 2a: per-row gathers (+ L2 prefetch of next step's streams) ----
        {
            if (lane == 0 && step + 1 < NSTEPS) {
                size_t basep = ((size_t)((step + 1) * Bm + rowBase)) * Dm + (warp << 5);
                #pragma unroll
                for (int m = 0; m < Mrows; m++) {
                    asm volatile("prefetch.global.L2 [%0];" :: "l"(rr + basep + (size_t)m * Dm));
                    asm volatile("prefetch.global.L2 [%0];" :: "l"(noise + basep + (size_t)m * Dm));
                }
            }
            const int g  = d & 63;
            const int rp = d >> 6;
            const char* wbase = (const char*)Wm + g * 16;
            #pragma unroll
            for (int t = 0; t < 2; t++) {
                const int m = rp + t * 4;
                const int cnt  = fcnt[m];
                const int full = cnt & ~3;
                const int* fl = flist[m];
                const int4* fl4 = reinterpret_cast<const int4*>(fl);
                float4 acc = *reinterpret_cast<const float4*>(&xh[m * Dm + g * 4]);
                int4 en = fl4[0];
                for (int i = 0; i < full; i += 4) {
                    int4 e = en;
                    en = fl4[(i >> 2) + 1];
                    float4 w0 = *reinterpret_cast<const float4*>(wbase + (e.x & OFMASK));
                    float4 w1 = *reinterpret_cast<const float4*>(wbase + (e.y & OFMASK));
                    float4 w2 = *reinterpret_cast<const float4*>(wbase + (e.z & OFMASK));
                    float4 w3 = *reinterpret_cast<const float4*>(wbase + (e.w & OFMASK));
                    acc.x += sxor(w0.x, e.x); acc.y += sxor(w0.y, e.x);
                    acc.z += sxor(w0.z, e.x); acc.w += sxor(w0.w, e.x);
                    acc.x += sxor(w1.x, e.y); acc.y += sxor(w1.y, e.y);
                    acc.z += sxor(w1.z, e.y); acc.w += sxor(w1.w, e.y);
                    acc.x += sxor(w2.x, e.z); acc.y += sxor(w2.y, e.z);
                    acc.z += sxor(w2.z, e.z); acc.w += sxor(w2.w, e.z);
                    acc.x += sxor(w3.x, e.w); acc.y += sxor(w3.y, e.w);
                    acc.z += sxor(w3.z, e.w); acc.w += sxor(w3.w, e.w);
                }
                if (cnt & 3) {   // one padded tail group: fmaf(sv in {+1,-1,0}) exact
                    #pragma unroll
                    for (int j = 0; j < 4; j++) {
                        int e = fl[full + j];
                        float sv = (e & PADB) ? 0.0f : ((e < 0) ? -1.0f : 1.0f);
                        float4 w = *reinterpret_cast<const float4*>(wbase + (e & OFMASK));
                        acc.x = fmaf(sv, w.x, acc.x);
                        acc.y = fmaf(sv, w.y, acc.y);
                        acc.z = fmaf(sv, w.z, acc.z);
                        acc.w = fmaf(sv, w.w, acc.w);
                    }
                }
                *reinterpret_cast<float4*>(&h2s[m][g * 4]) = acc;
            }
        }
        __syncthreads();

        // ---- stage 2b: reverse terms + per-row la reduce (owner thread d) ----
        #pragma unroll
        for (int m = 0; m < Mrows; m++) {
            float acc  = h2s[m][d];
            float xdav = xdas[m][d];
            float xf   = ((xmask >> m) & 1u) ? 1.0f : 0.0f;
            bool  ind  = (indmask >> m) & 1u;
            float xdv  = ind ? 1.0f - xf : xf;
            float sgn2 = 1.0f - 2.0f * xdv;
            float ga2  = (xdv - xdav) * 1e-4f;
            float hb2  = acc + bd;
            float gm2  = (hb2 * sgn2) * 0.5f - (ga2 * 0.5f) * sgn2;
            float fp2  = my_sigmoid(gm2 - 2.5f);
            float lpr  = my_log((ind ? fp2 : 1.0f - fp2) + 1e-10f);
            float e2   = (xdv != 0.0f) ? fmaf(0.5f, acc, bd) : 0.0f;
            float dxd  = xdv - xdav;
            float inner2 = fmaf(0.25f, ga2, xdav);
            float q2   = xa[m] - inner2;
            float t = taccs[m][d] + lpr + e2 - fmaf(dxd * dxd, 5e-5f, q2 * q2);

            t += __shfl_down_sync(0xffffffffu, t, 16);
            t += __shfl_down_sync(0xffffffffu, t, 8);
            t += __shfl_down_sync(0xffffffffu, t, 4);
            t += __shfl_down_sync(0xffffffffu, t, 2);
            t += __shfl_down_sync(0xffffffffu, t, 1);
            if (lane == 0) red[m][warp] = t;
        }
        __syncthreads();

        // ---- MH accept: every warp redundantly computes all 8 flags ----
        // lanes 0..7: row = lane; identical inputs + identical ascending sum
        // order as an 8-thread stage => bit-identical accept decisions.
        float accv = 0.0f;
        if (lane < Mrows) {
            float la = 0.0f;
            #pragma unroll
            for (int w2 = 0; w2 < NW; w2++) la += red[lane][w2];
            float u = __ldcs(&au[step * Bm + rowBase + lane]);
            float lu = (u > 0.0f) ? my_log(u) : -3.0e38f;
            accv = (la > lu) ? 1.0f : 0.0f;
        }
        // ---- commit immediately (no second barrier): broadcast via shfl ----
        #pragma unroll
        for (int m = 0; m < Mrows; m++) {
            float am = __shfl_sync(0xffffffffu, accv, m);
            if (am != 0.0f) {
                xa[m] = xdas[m][d];
                xh[m * Dm + d] = h2s[m][d];
                xmask ^= (indmask & (1u << m));
            }
        }
        // no __syncthreads: commit wrote only this thread's own xh slot; red[][]
        // is re-written next step only after the stage-1-end barrier.
    }

    #pragma unroll
    for (int m = 0; m < Mrows; m++) {
        float xf = ((xmask >> m) & 1u) ? 1.0f : 0.0f;
        __stcs(&out[(size_t)(rowBase + m) * Dm + d], xf);
        __stcs(&out[(size_t)Bm * Dm + (size_t)(rowBase + m) * Dm + d], xa[m]);
    }
}

extern "C" void kernel_launch(void* const* d_in, const int* in_sizes, int n_in,
                              void* d_out, int out_size) {
    const float* x  = (const float*)d_in[0];
    const float* xa = (const float*)d_in[1];
    const float* W  = (const float*)d_in[2];
    const float* b  = (const float*)d_in[3];
    const float* rr = (const float*)d_in[4];
    const float* nz = (const float*)d_in[5];
    const float* au = (const float*)d_in[6];
    els_kernel<<<Bm / Mrows, 256>>>(x, xa, W, b, rr, nz, au, (float*)d_out);
}

// round 17
// speedup vs baseline: 1.0074x; 1.0074x over previous
#include <cuda_runtime.h>
#include <stdint.h>

#define Dm 256
#define Bm 16384
#define NSTEPS 5
#define Mrows 8
#define NW 8
#define LCAP 264

#define SIGNB 0x80000000
#define PADB  0x40000000
#define OFMASK 0x0003FC00   // idx<<10 (byte offset of W row) for idx<256

// ---- flag-independent fp32 exp/log/sigmoid (pure FMA; sigmoid keeps __fdiv_rn) ----

static __device__ __forceinline__ float my_exp(float x) {
    x = fmaxf(x, -80.0f);
    float z = x * 1.4426950408889634f;
    float n = rintf(z);
    float r = fmaf(n, -0.693359375f, x);
    r = fmaf(n, 2.12194440054690583e-4f, r);
    float p = 1.9841269841269841e-4f;
    p = fmaf(p, r, 1.3888888888888889e-3f);
    p = fmaf(p, r, 8.3333333333333333e-3f);
    p = fmaf(p, r, 4.1666666666666664e-2f);
    p = fmaf(p, r, 1.6666666666666666e-1f);
    p = fmaf(p, r, 0.5f);
    p = fmaf(p, r, 1.0f);
    p = fmaf(p, r, 1.0f);
    int ni = (int)n;
    return p * __int_as_float((127 + ni) << 23);
}

static __device__ __forceinline__ float my_log(float v) {
    int i = __float_as_int(v);
    int e = (i - 0x3f3504f3) >> 23;
    float m = __int_as_float(i - (e << 23));
    float f = m - 1.0f;
    float z = f * f;
    float p = 7.0376836292e-2f;
    p = fmaf(p, f, -1.1514610310e-1f);
    p = fmaf(p, f, 1.1676998740e-1f);
    p = fmaf(p, f, -1.2420140846e-1f);
    p = fmaf(p, f, 1.4249322787e-1f);
    p = fmaf(p, f, -1.6668057665e-1f);
    p = fmaf(p, f, 2.0000714765e-1f);
    p = fmaf(p, f, -2.4999993993e-1f);
    p = fmaf(p, f, 3.3333331174e-1f);
    float r = fmaf(p * z, f, fmaf(-0.5f, z, f));
    float ef = (float)e;
    return fmaf(ef, 0.693359375f, fmaf(ef, -2.12194440054690583e-4f, r));
}

static __device__ __forceinline__ float my_sigmoid(float t) {   // decision-critical: unchanged
    float en = my_exp(-fabsf(t));
    float s = __fdiv_rn(en, 1.0f + en);
    return (t > 0.0f) ? 1.0f - s : s;
}

static __device__ __forceinline__ float sxor(float w, int e) {  // w * sign(e) via bit xor
    return __int_as_float(__float_as_int(w) ^ (e & SIGNB));
}

// ---- fused sampler: one block = 8 chains; thread d owns dim d for math,
// ---- gathers re-map to (64 dim-quads x 4 row-pairs) with LDG.128 ----

__global__ void __launch_bounds__(256, 4)
els_kernel(const float* __restrict__ x_in, const float* __restrict__ xa_in,
           const float* __restrict__ Wm, const float* __restrict__ bv,
           const float* __restrict__ rr, const float* __restrict__ noise,
           const float* __restrict__ au, float* __restrict__ out)
{
    const int d = threadIdx.x;
    const int warp = d >> 5;
    const int lane = d & 31;
    const int rowBase = blockIdx.x * Mrows;

    __shared__ float   xh[Mrows * Dm];         // h state, [m*256 + d]
    __shared__ unsigned posw[Mrows][NW];       // per-step: indball (ballot of ind)
    __shared__ unsigned negw[Mrows][NW];       // persistent: xball (ballot of x!=0)
    __shared__ int     flist[Mrows][LCAP];     // packed: sign | (idx<<10); PADB = pad
    __shared__ int     fcnt[Mrows];            // exact count
    __shared__ float   red[Mrows][NW];
    __shared__ float   xdas[Mrows][Dm];
    __shared__ float   taccs[Mrows][Dm];
    __shared__ float   h2s[Mrows][Dm];

    const float bd = bv[d];
    float xa[Mrows];
    unsigned xmask = 0;

    // ---- load x/xa; ballot x-bits: posw = init ones-list mask, negw = xball ----
    #pragma unroll
    for (int m = 0; m < Mrows; m++) {
        float xv = __ldcs(&x_in[(size_t)(rowBase + m) * Dm + d]);
        xa[m] = __ldcs(&xa_in[(size_t)(rowBase + m) * Dm + d]);
        bool one = xv != 0.0f;
        if (one) xmask |= (1u << m);
        unsigned pb = __ballot_sync(0xffffffffu, one);
        if (lane == 0) { posw[m][warp] = pb; negw[m][warp] = pb; }
    }
    // prefetch step-0 rr/noise lines + au lines into L2 while init runs
    if (lane == 0) {
        size_t base0 = (size_t)rowBase * Dm + (warp << 5);
        #pragma unroll
        for (int m = 0; m < Mrows; m++) {
            asm volatile("prefetch.global.L2 [%0];" :: "l"(rr + base0 + (size_t)m * Dm));
            asm volatile("prefetch.global.L2 [%0];" :: "l"(noise + base0 + (size_t)m * Dm));
        }
    }
    if (d == 0) {
        #pragma unroll
        for (int s = 0; s < NSTEPS; s++)
            asm volatile("prefetch.global.L2 [%0];" :: "l"(au + (size_t)s * Bm + rowBase));
    }
    __syncthreads();

    // ---- build init lists (64 threads; ones of x as positive entries) ----
    if (d < Mrows * NW) {
        int m = d >> 3, c = d & 7;
        int off = 0;
        #pragma unroll
        for (int c2 = 0; c2 < NW; c2++) {
            int cnt = __popc(posw[m][c2]);
            if (c2 < c) off += cnt;
        }
        int base = c * 32;
        unsigned pw = posw[m][c];
        while (pw) { int j = __ffs(pw) - 1; pw &= pw - 1; flist[m][off++] = (base + j) << 10; }
        if (c == NW - 1) {
            int padded = (off + 3) & ~3;
            for (int i = off; i < padded; i++) flist[m][i] = PADB;
            fcnt[m] = off;
        }
    }
    __syncthreads();

    // ---- init gather: h = sum_{e: x=1} W[e][:]  (== FMA loop skipping exact
    // ---- zeros, ascending e => bit-identical to the dense matvec) ----
    {
        const int g  = d & 63;
        const int rp = d >> 6;
        const char* wbase = (const char*)Wm + g * 16;
        #pragma unroll
        for (int t = 0; t < 2; t++) {
            const int m = rp + t * 4;
            const int cnt  = fcnt[m];
            const int full = cnt & ~3;
            const int* fl = flist[m];
            const int4* fl4 = reinterpret_cast<const int4*>(fl);
            float4 acc = make_float4(0.0f, 0.0f, 0.0f, 0.0f);
            int4 en = fl4[0];
            for (int i = 0; i < full; i += 4) {
                int4 e = en;
                en = fl4[(i >> 2) + 1];
                float4 w0 = *reinterpret_cast<const float4*>(wbase + (e.x & OFMASK));
                float4 w1 = *reinterpret_cast<const float4*>(wbase + (e.y & OFMASK));
                float4 w2 = *reinterpret_cast<const float4*>(wbase + (e.z & OFMASK));
                float4 w3 = *reinterpret_cast<const float4*>(wbase + (e.w & OFMASK));
                acc.x += w0.x; acc.y += w0.y; acc.z += w0.z; acc.w += w0.w;
                acc.x += w1.x; acc.y += w1.y; acc.z += w1.z; acc.w += w1.w;
                acc.x += w2.x; acc.y += w2.y; acc.z += w2.z; acc.w += w2.w;
                acc.x += w3.x; acc.y += w3.y; acc.z += w3.z; acc.w += w3.w;
            }
            if (cnt & 3) {
                #pragma unroll
                for (int j = 0; j < 4; j++) {
                    int e = fl[full + j];
                    float sv = (e & PADB) ? 0.0f : 1.0f;
                    float4 w = *reinterpret_cast<const float4*>(wbase + (e & OFMASK));
                    acc.x = fmaf(sv, w.x, acc.x);
                    acc.y = fmaf(sv, w.y, acc.y);
                    acc.z = fmaf(sv, w.z, acc.z);
                    acc.w = fmaf(sv, w.w, acc.w);
                }
            }
            *reinterpret_cast<float4*>(&xh[m * Dm + g * 4]) = acc;
        }
    }
    __syncthreads();

    for (int step = 0; step < NSTEPS; step++) {
        unsigned indmask = 0;

        // ---- stage 1: propose flips, forward log-prob terms (ONE ballot/row) ----
        #pragma unroll
        for (int m = 0; m < Mrows; m++) {
            float rv  = __ldcs(&rr[((size_t)(step * Bm + rowBase + m)) * Dm + d]);
            float nv  = __ldcs(&noise[((size_t)(step * Bm + rowBase + m)) * Dm + d]);
            float hm  = xh[m * Dm + d];
            float xf  = ((xmask >> m) & 1u) ? 1.0f : 0.0f;
            float sgn = 1.0f - 2.0f * xf;                    // -(2x-1)
            float ga  = (xf - xa[m]) * 1e-4f;                // (x - xa)/ETA
            float hb  = hm + bd;
            float gm  = (hb * sgn) * 0.5f - (ga * 0.5f) * sgn;
            float fp  = my_sigmoid(gm - 2.5f);
            bool ind  = rv < fp;
            float inner = xa[m] + 0.25f * ga;
            float pn  = __fmul_rn(0.70710678118654752f, nv);
            float xdav = inner + pn;
            float lpf = my_log((ind ? fp : 1.0f - fp) + 1e-10f);
            float e1  = (xf != 0.0f) ? fmaf(0.5f, hm, bd) : 0.0f;  // x*(0.5h+b)
            float dxa = xf - xa[m];
            float q1  = xdav - inner;
            taccs[m][d] = fmaf(dxa * dxa, 5e-5f, q1 * q1) - lpf - e1;
            if (ind) indmask |= (1u << m);
            unsigned ib = __ballot_sync(0xffffffffu, ind);
            if (lane == 0) posw[m][warp] = ib;   // indball; pb/nb derived in 1b
            xdas[m][d] = xdav;
        }
        __syncthreads();

        // ---- stage 1b: pb = ib & ~xball, nb = ib & xball (bit-identical lists) ----
        // Order per row: chunk 0..7, pos asc then neg asc (bit-identical h2 order).
        if (d < Mrows * NW) {
            int m = d >> 3, c = d & 7;
            int off = 0;
            #pragma unroll
            for (int c2 = 0; c2 < NW; c2++) {
                int cnt = __popc(posw[m][c2]);     // popc(pb)+popc(nb) == popc(ib)
                if (c2 < c) off += cnt;
            }
            unsigned ib = posw[m][c];
            unsigned xb = negw[m][c];
            int base = c * 32;
            unsigned pw = ib & ~xb;
            while (pw) { int j = __ffs(pw) - 1; pw &= pw - 1; flist[m][off++] = (base + j) << 10; }
            unsigned nw_ = ib & xb;
            while (nw_) { int j = __ffs(nw_) - 1; nw_ &= nw_ - 1; flist[m][off++] = (int)(SIGNB | (unsigned)((base + j) << 10)); }
            if (c == NW - 1) {
                int padded = (off + 3) & ~3;
                for (int i = off; i < padded; i++) flist[m][i] = PADB;
                fcnt[m] = off;
            }
        }
        __syncthreads();

        // ---- stage 2a: per-row gathers (+ L2 prefetch of next step's streams) ----
        {
            if (lane == 0 && step + 1 < NSTEPS) {
                size_t basep = ((size_t)((step + 1) * Bm + rowBase)) * Dm + (warp << 5);
                #pragma unroll
                for (int m = 0; m < Mrows; m++) {
                    asm volatile("prefetch.global.L2 [%0];" :: "l"(rr + basep + (size_t)m * Dm));
                    asm volatile("prefetch.global.L2 [%0];" :: "l"(noise + basep + (size_t)m * Dm));
                }
            }
            const int g  = d & 63;
            const int rp = d >> 6;
            const char* wbase = (const char*)Wm + g * 16;
            #pragma unroll
            for (int t = 0; t < 2; t++) {
                const int m = rp + t * 4;
                const int cnt  = fcnt[m];
                const int full = cnt & ~3;
                const int* fl = flist[m];
                const int4* fl4 = reinterpret_cast<const int4*>(fl);
                float4 acc = *reinterpret_cast<const float4*>(&xh[m * Dm + g * 4]);
                int4 en = fl4[0];
                for (int i = 0; i < full; i += 4) {
                    int4 e = en;
                    en = fl4[(i >> 2) + 1];
                    float4 w0 = *reinterpret_cast<const float4*>(wbase + (e.x & OFMASK));
                    float4 w1 = *reinterpret_cast<const float4*>(wbase + (e.y & OFMASK));
                    float4 w2 = *reinterpret_cast<const float4*>(wbase + (e.z & OFMASK));
                    float4 w3 = *reinterpret_cast<const float4*>(wbase + (e.w & OFMASK));
                    acc.x += sxor(w0.x, e.x); acc.y += sxor(w0.y, e.x);
                    acc.z += sxor(w0.z, e.x); acc.w += sxor(w0.w, e.x);
                    acc.x += sxor(w1.x, e.y); acc.y += sxor(w1.y, e.y);
                    acc.z += sxor(w1.z, e.y); acc.w += sxor(w1.w, e.y);
                    acc.x += sxor(w2.x, e.z); acc.y += sxor(w2.y, e.z);
                    acc.z += sxor(w2.z, e.z); acc.w += sxor(w2.w, e.z);
                    acc.x += sxor(w3.x, e.w); acc.y += sxor(w3.y, e.w);
                    acc.z += sxor(w3.z, e.w); acc.w += sxor(w3.w, e.w);
                }
                if (cnt & 3) {   // one padded tail group: fmaf(sv in {+1,-1,0}) exact
                    #pragma unroll
                    for (int j = 0; j < 4; j++) {
                        int e = fl[full + j];
                        float sv = (e & PADB) ? 0.0f : ((e < 0) ? -1.0f : 1.0f);
                        float4 w = *reinterpret_cast<const float4*>(wbase + (e & OFMASK));
                        acc.x = fmaf(sv, w.x, acc.x);
                        acc.y = fmaf(sv, w.y, acc.y);
                        acc.z = fmaf(sv, w.z, acc.z);
                        acc.w = fmaf(sv, w.w, acc.w);
                    }
                }
                *reinterpret_cast<float4*>(&h2s[m][g * 4]) = acc;
            }
        }
        __syncthreads();

        // ---- stage 2b: reverse terms + per-row la reduce (owner thread d) ----
        #pragma unroll
        for (int m = 0; m < Mrows; m++) {
            float acc  = h2s[m][d];
            float xdav = xdas[m][d];
            float xf   = ((xmask >> m) & 1u) ? 1.0f : 0.0f;
            bool  ind  = (indmask >> m) & 1u;
            float xdv  = ind ? 1.0f - xf : xf;
            float sgn2 = 1.0f - 2.0f * xdv;
            float ga2  = (xdv - xdav) * 1e-4f;
            float hb2  = acc + bd;
            float gm2  = (hb2 * sgn2) * 0.5f - (ga2 * 0.5f) * sgn2;
            float fp2  = my_sigmoid(gm2 - 2.5f);
            float lpr  = my_log((ind ? fp2 : 1.0f - fp2) + 1e-10f);
            float e2   = (xdv != 0.0f) ? fmaf(0.5f, acc, bd) : 0.0f;
            float dxd  = xdv - xdav;
            float inner2 = fmaf(0.25f, ga2, xdav);
            float q2   = xa[m] - inner2;
            float t = taccs[m][d] + lpr + e2 - fmaf(dxd * dxd, 5e-5f, q2 * q2);

            t += __shfl_down_sync(0xffffffffu, t, 16);
            t += __shfl_down_sync(0xffffffffu, t, 8);
            t += __shfl_down_sync(0xffffffffu, t, 4);
            t += __shfl_down_sync(0xffffffffu, t, 2);
            t += __shfl_down_sync(0xffffffffu, t, 1);
            if (lane == 0) red[m][warp] = t;
        }
        __syncthreads();

        // ---- MH accept: every warp redundantly computes all 8 flags ----
        // lanes 0..7: row = lane; identical inputs + identical ascending sum
        // order as an 8-thread stage => bit-identical accept decisions.
        float accv = 0.0f;
        if (lane < Mrows) {
            float la = 0.0f;
            #pragma unroll
            for (int w2 = 0; w2 < NW; w2++) la += red[lane][w2];
            float u = __ldcs(&au[step * Bm + rowBase + lane]);
            float lu = (u > 0.0f) ? my_log(u) : -3.0e38f;
            accv = (la > lu) ? 1.0f : 0.0f;
        }
        // maintain xball: on accept, x flips exactly where ind=1 (this warp's chunk).
        // Unique (row, warp) slot per thread; next reader (1b) is behind two barriers.
        if (lane < Mrows && accv != 0.0f)
            negw[lane][warp] ^= posw[lane][warp];
        // ---- commit immediately (no second barrier): broadcast via shfl ----
        #pragma unroll
        for (int m = 0; m < Mrows; m++) {
            float am = __shfl_sync(0xffffffffu, accv, m);
            if (am != 0.0f) {
                xa[m] = xdas[m][d];
                xh[m * Dm + d] = h2s[m][d];
                xmask ^= (indmask & (1u << m));
            }
        }
        // no __syncthreads: commit wrote only this thread's own xh/negw slots;
        // cross-thread readers are behind the stage-1-end barrier.
    }

    #pragma unroll
    for (int m = 0; m < Mrows; m++) {
        float xf = ((xmask >> m) & 1u) ? 1.0f : 0.0f;
        __stcs(&out[(size_t)(rowBase + m) * Dm + d], xf);
        __stcs(&out[(size_t)Bm * Dm + (size_t)(rowBase + m) * Dm + d], xa[m]);
    }
}

extern "C" void kernel_launch(void* const* d_in, const int* in_sizes, int n_in,
                              void* d_out, int out_size) {
    const float* x  = (const float*)d_in[0];
    const float* xa = (const float*)d_in[1];
    const float* W  = (const float*)d_in[2];
    const float* b  = (const float*)d_in[3];
    const float* rr = (const float*)d_in[4];
    const float* nz = (const float*)d_in[5];
    const float* au = (const float*)d_in[6];
    els_kernel<<<Bm / Mrows, 256>>>(x, xa, W, b, rr, nz, au, (float*)d_out);
}